// round 1
// baseline (speedup 1.0000x reference)
#include <cuda_runtime.h>
#include <cuda_bf16.h>
#include <cstdint>

#define NUM_USERS 20000
#define EMBED_DIM 64
#define KSEL 6          // K+1 = 6 candidates, drop the max, keep 5
#define KNB  5
#define THREADS 256
#define BATCH 4096
#define ROW4 (NUM_USERS / 4)   // 5000 float4 per row

static __device__ __forceinline__ unsigned long long umax64(unsigned long long a,
                                                            unsigned long long b) {
    return a > b ? a : b;
}

__global__ __launch_bounds__(THREADS)
void topk_blend_kernel(const int* __restrict__ user_idx,
                       const float* __restrict__ emb,
                       const float* __restrict__ cooc,
                       float* __restrict__ out)
{
    const int b   = blockIdx.x;
    const int tid = threadIdx.x;
    const int u   = user_idx[b];

    const float4* row4 = reinterpret_cast<const float4*>(cooc + (size_t)u * NUM_USERS);

    // ---- per-thread top-6 (descending) of packed (valbits<<32)|~idx keys ----
    unsigned long long top[KSEL];
#pragma unroll
    for (int i = 0; i < KSEL; i++) top[i] = 0ULL;

    for (int i = tid; i < ROW4; i += THREADS) {
        float4 v = row4[i];
        unsigned base = (unsigned)(i * 4);
#pragma unroll
        for (int c = 0; c < 4; c++) {
            float f = (c == 0) ? v.x : (c == 1) ? v.y : (c == 2) ? v.z : v.w;
            unsigned long long key =
                ((unsigned long long)__float_as_uint(f) << 32) | (unsigned)(~(base + c));
            if (key > top[KSEL - 1]) {
                int j = KSEL - 1;
#pragma unroll
                for (int s = KSEL - 1; s > 0; s--) {
                    if (j > 0 && key > top[j - 1]) { top[j] = top[j - 1]; j--; }
                }
                top[j] = key;
            }
        }
    }

    // ---- block-wide selection of global top-6: 6 rounds of u64 max-reduce ----
    __shared__ unsigned long long warp_max[THREADS / 32];
    __shared__ unsigned long long winners[KSEL];

    int ptr = 0;  // how many of my local top-6 have been consumed globally
#pragma unroll
    for (int r = 0; r < KSEL; r++) {
        unsigned long long cand = (ptr < KSEL) ? top[ptr] : 0ULL;
        unsigned long long m = cand;
#pragma unroll
        for (int off = 16; off > 0; off >>= 1)
            m = umax64(m, __shfl_xor_sync(0xffffffffu, m, off));
        if ((tid & 31) == 0) warp_max[tid >> 5] = m;
        __syncthreads();
        if (tid < 32) {
            unsigned long long mm = (tid < (THREADS / 32)) ? warp_max[tid] : 0ULL;
#pragma unroll
            for (int off = 4; off > 0; off >>= 1)
                mm = umax64(mm, __shfl_xor_sync(0xffffffffu, mm, off));
            if (tid == 0) winners[r] = mm;
        }
        __syncthreads();
        // exactly one thread holds the winner (idx embedded -> keys unique)
        if (ptr < KSEL && cand == winners[r]) ptr++;
    }

    // ---- epilogue: softmax over winners[1..5], blend embeddings ----
    if (tid < EMBED_DIM) {
        // winners[0] is the dropped top-1; winners[1] is the max of the kept 5
        float smax = __uint_as_float((unsigned)(winners[1] >> 32));
        float sum = 0.0f;
        float acc = 0.0f;
#pragma unroll
        for (int j = 0; j < KNB; j++) {
            unsigned long long k = winners[j + 1];
            float    s    = __uint_as_float((unsigned)(k >> 32));
            unsigned sidx = ~(unsigned)(k & 0xffffffffULL);
            float    e    = __expf(s - smax);
            sum += e;
            acc  = fmaf(e, emb[(size_t)sidx * EMBED_DIM + tid], acc);
        }
        float blended = acc / sum;
        out[(size_t)b * EMBED_DIM + tid] =
            fmaf(0.7f, emb[(size_t)u * EMBED_DIM + tid], 0.3f * blended);
    }
}

extern "C" void kernel_launch(void* const* d_in, const int* in_sizes, int n_in,
                              void* d_out, int out_size)
{
    const int*   user_idx = (const int*)d_in[0];
    const float* emb      = (const float*)d_in[1];
    const float* cooc     = (const float*)d_in[2];
    float*       out      = (float*)d_out;

    topk_blend_kernel<<<BATCH, THREADS>>>(user_idx, emb, cooc, out);
}

// round 2
// speedup vs baseline: 1.0139x; 1.0139x over previous
#include <cuda_runtime.h>
#include <cuda_bf16.h>
#include <cstdint>

#define NUM_USERS 20000
#define EMBED_DIM 64
#define KSEL 6          // K+1 = 6 candidates, drop the max, keep 5
#define KNB  5
#define THREADS 256
#define BATCH 4096
#define ROW4 (NUM_USERS / 4)        // 5000 float4 per row
#define UNROLL 4
#define SUPER (THREADS * UNROLL)    // 1024 float4 per superblock
#define NSUPER ((ROW4 + SUPER - 1) / SUPER)  // 5

static __device__ __forceinline__ unsigned long long umax64(unsigned long long a,
                                                            unsigned long long b) {
    return a > b ? a : b;
}

__global__ __launch_bounds__(THREADS)
void topk_blend_kernel(const int* __restrict__ user_idx,
                       const float* __restrict__ emb,
                       const float* __restrict__ cooc,
                       float* __restrict__ out)
{
    const int b   = blockIdx.x;
    const int tid = threadIdx.x;
    const int u   = user_idx[b];

    const float4* row4 = reinterpret_cast<const float4*>(cooc + (size_t)u * NUM_USERS);

    // ---- per-thread top-6 as packed (valbits<<32)|~idx keys, with a float
    //      threshold mirror of the 6th-best value for the fast-path filter ----
    unsigned long long top[KSEL];
#pragma unroll
    for (int i = 0; i < KSEL; i++) top[i] = 0ULL;
    float thresh = 0.0f;

#pragma unroll
    for (int s = 0; s < NSUPER; s++) {
        const int i0 = s * SUPER + tid;

        // Batch 4 independent 16B loads -> MLP >= 4 per warp.
        float4 v[UNROLL];
#pragma unroll
        for (int j = 0; j < UNROLL; j++) {
            int ii = i0 + j * THREADS;
            bool ok = (ii < ROW4);
            v[j] = row4[ok ? ii : 0];
            if (!ok) { v[j].x = v[j].y = v[j].z = v[j].w = -1.0f; }
        }

        // Branchless fast path: 15-op max tree + single compare.
        float m = -1.0f;
#pragma unroll
        for (int j = 0; j < UNROLL; j++)
            m = fmaxf(m, fmaxf(fmaxf(v[j].x, v[j].y), fmaxf(v[j].z, v[j].w)));

        if (m > thresh) {
            // Rare slow path: at least one candidate in this 16-element block.
#pragma unroll
            for (int j = 0; j < UNROLL; j++) {
                const unsigned base = (unsigned)((i0 + j * THREADS) * 4);
#pragma unroll
                for (int c = 0; c < 4; c++) {
                    float f = (c == 0) ? v[j].x : (c == 1) ? v[j].y
                             : (c == 2) ? v[j].z : v[j].w;
                    if (f > thresh) {
                        // f > value(top[5]) strictly => key > top[5] guaranteed.
                        unsigned long long key =
                            ((unsigned long long)__float_as_uint(f) << 32) |
                            (unsigned)(~(base + c));
                        int p = KSEL - 1;
#pragma unroll
                        for (int t = KSEL - 1; t > 0; t--) {
                            if (p > 0 && key > top[p - 1]) { top[p] = top[p - 1]; p--; }
                        }
                        top[p] = key;
                        thresh = __uint_as_float((unsigned)(top[KSEL - 1] >> 32));
                    }
                }
            }
        }
    }

    // ---- block-wide selection of global top-6: 6 rounds of u64 max-reduce ----
    __shared__ unsigned long long warp_max[THREADS / 32];
    __shared__ unsigned long long winners[KSEL];

    int ptr = 0;  // how many of my local top-6 have been consumed globally
#pragma unroll
    for (int r = 0; r < KSEL; r++) {
        unsigned long long cand = (ptr < KSEL) ? top[ptr] : 0ULL;
        unsigned long long m = cand;
#pragma unroll
        for (int off = 16; off > 0; off >>= 1)
            m = umax64(m, __shfl_xor_sync(0xffffffffu, m, off));
        if ((tid & 31) == 0) warp_max[tid >> 5] = m;
        __syncthreads();
        if (tid < 32) {
            unsigned long long mm = (tid < (THREADS / 32)) ? warp_max[tid] : 0ULL;
#pragma unroll
            for (int off = 4; off > 0; off >>= 1)
                mm = umax64(mm, __shfl_xor_sync(0xffffffffu, mm, off));
            if (tid == 0) winners[r] = mm;
        }
        __syncthreads();
        // keys are unique (idx embedded) -> exactly one thread advances
        if (ptr < KSEL && cand == winners[r]) ptr++;
    }

    // ---- epilogue: softmax over winners[1..5], blend embeddings ----
    if (tid < EMBED_DIM) {
        float smax = __uint_as_float((unsigned)(winners[1] >> 32));
        float sum = 0.0f;
        float acc = 0.0f;
#pragma unroll
        for (int j = 0; j < KNB; j++) {
            unsigned long long k = winners[j + 1];
            float    s    = __uint_as_float((unsigned)(k >> 32));
            unsigned sidx = ~(unsigned)(k & 0xffffffffULL);
            float    e    = __expf(s - smax);
            sum += e;
            acc  = fmaf(e, emb[(size_t)sidx * EMBED_DIM + tid], acc);
        }
        float blended = acc / sum;
        out[(size_t)b * EMBED_DIM + tid] =
            fmaf(0.7f, emb[(size_t)u * EMBED_DIM + tid], 0.3f * blended);
    }
}

extern "C" void kernel_launch(void* const* d_in, const int* in_sizes, int n_in,
                              void* d_out, int out_size)
{
    const int*   user_idx = (const int*)d_in[0];
    const float* emb      = (const float*)d_in[1];
    const float* cooc     = (const float*)d_in[2];
    float*       out      = (float*)d_out;

    topk_blend_kernel<<<BATCH, THREADS>>>(user_idx, emb, cooc, out);
}

// round 5
// speedup vs baseline: 1.9932x; 1.9659x over previous
#include <cuda_runtime.h>
#include <cuda_bf16.h>
#include <cstdint>

#define NUM_USERS 20000
#define EMBED_DIM 64
#define KSEL 6          // K+1 = 6 candidates, drop the max, keep 5
#define KNB  5
#define THREADS 256
#define BATCH 4096
#define ROW4 (NUM_USERS / 4)        // 5000 float4 per row
#define UNROLL 5
#define SUPER (THREADS * UNROLL)    // 1280 float4 per superblock
#define NSUPER 4                    // 4*1280 = 5120 >= 5000

static __device__ __forceinline__ unsigned long long umax64(unsigned long long a,
                                                            unsigned long long b) {
    return a > b ? a : b;
}

// Branchless sorted insert into a descending register array. All indices are
// compile-time constants -> stays in registers (no local memory).
static __device__ __forceinline__ void insert6(unsigned long long (&top)[KSEL],
                                               unsigned long long key) {
#pragma unroll
    for (int i = 0; i < KSEL; i++) {
        unsigned long long hi = (top[i] > key) ? top[i] : key;
        unsigned long long lo = (top[i] > key) ? key : top[i];
        top[i] = hi;
        key = lo;
    }
}

__global__ void __launch_bounds__(THREADS, 4)
topk_blend_kernel(const int* __restrict__ user_idx,
                  const float* __restrict__ emb,
                  const float* __restrict__ cooc,
                  float* __restrict__ out)
{
    const int b   = blockIdx.x;
    const int tid = threadIdx.x;
    const int u   = user_idx[b];

    const float4* row4 = reinterpret_cast<const float4*>(cooc + (size_t)u * NUM_USERS);

    unsigned long long top[KSEL];
#pragma unroll
    for (int i = 0; i < KSEL; i++) top[i] = 0ULL;
    float thresh = 0.0f;   // value of current 6th-best (mirror of top[5])

#pragma unroll
    for (int s = 0; s < NSUPER; s++) {
        const int i0 = s * SUPER + tid;

        // 5 independent 16B loads issued back-to-back -> MLP >= 5 per thread.
        float4 v[UNROLL];
#pragma unroll
        for (int j = 0; j < UNROLL; j++) {
            int ii = i0 + j * THREADS;
            bool ok = (ii < ROW4);
            v[j] = row4[ok ? ii : 0];
            if (!ok) { v[j].x = v[j].y = v[j].z = v[j].w = -1.0f; }
        }

        // Branchless fast path: max tree over 20 values + one compare.
        float m = -1.0f;
#pragma unroll
        for (int j = 0; j < UNROLL; j++)
            m = fmaxf(m, fmaxf(fmaxf(v[j].x, v[j].y), fmaxf(v[j].z, v[j].w)));

        if (m > thresh) {
            // Rare slow path: insert every candidate above the old threshold.
#pragma unroll
            for (int j = 0; j < UNROLL; j++) {
                const unsigned base = (unsigned)((i0 + j * THREADS) * 4);
#pragma unroll
                for (int c = 0; c < 4; c++) {
                    float f = (c == 0) ? v[j].x : (c == 1) ? v[j].y
                             : (c == 2) ? v[j].z : v[j].w;
                    if (f > thresh) {
                        unsigned long long key =
                            ((unsigned long long)__float_as_uint(f) << 32) |
                            (unsigned)(~(base + c));
                        insert6(top, key);
                    }
                }
            }
            thresh = __uint_as_float((unsigned)(top[KSEL - 1] >> 32));
        }
    }

    // ---- block-wide selection of global top-6: 6 rounds of u64 max-reduce ----
    __shared__ unsigned long long warp_max[THREADS / 32];
    __shared__ unsigned long long winners[KSEL];

    int ptr = 0;
#pragma unroll
    for (int r = 0; r < KSEL; r++) {
        unsigned long long cand;
        // static access into top[] via small switch keeps it in registers
        switch (ptr) {
            case 0: cand = top[0]; break;
            case 1: cand = top[1]; break;
            case 2: cand = top[2]; break;
            case 3: cand = top[3]; break;
            case 4: cand = top[4]; break;
            case 5: cand = top[5]; break;
            default: cand = 0ULL; break;
        }
        unsigned long long m = cand;
#pragma unroll
        for (int off = 16; off > 0; off >>= 1)
            m = umax64(m, __shfl_xor_sync(0xffffffffu, m, off));
        if ((tid & 31) == 0) warp_max[tid >> 5] = m;
        __syncthreads();
        if (tid < 32) {
            unsigned long long mm = (tid < (THREADS / 32)) ? warp_max[tid] : 0ULL;
#pragma unroll
            for (int off = 4; off > 0; off >>= 1)
                mm = umax64(mm, __shfl_xor_sync(0xffffffffu, mm, off));
            if (tid == 0) winners[r] = mm;
        }
        __syncthreads();
        // keys are unique (idx embedded) -> exactly one thread advances
        if (ptr < KSEL && cand == winners[r]) ptr++;
    }

    // ---- epilogue: softmax over winners[1..5], blend embeddings ----
    if (tid < EMBED_DIM) {
        float smax = __uint_as_float((unsigned)(winners[1] >> 32));
        float sum = 0.0f;
        float acc = 0.0f;
#pragma unroll
        for (int j = 0; j < KNB; j++) {
            unsigned long long k = winners[j + 1];
            float    s    = __uint_as_float((unsigned)(k >> 32));
            unsigned sidx = ~(unsigned)(k & 0xffffffffULL);
            float    e    = __expf(s - smax);
            sum += e;
            acc  = fmaf(e, emb[(size_t)sidx * EMBED_DIM + tid], acc);
        }
        float blended = acc / sum;
        out[(size_t)b * EMBED_DIM + tid] =
            fmaf(0.7f, emb[(size_t)u * EMBED_DIM + tid], 0.3f * blended);
    }
}

extern "C" void kernel_launch(void* const* d_in, const int* in_sizes, int n_in,
                              void* d_out, int out_size)
{
    const int*   user_idx = (const int*)d_in[0];
    const float* emb      = (const float*)d_in[1];
    const float* cooc     = (const float*)d_in[2];
    float*       out      = (float*)d_out;

    topk_blend_kernel<<<BATCH, THREADS>>>(user_idx, emb, cooc, out);
}

// round 6
// speedup vs baseline: 3.8630x; 1.9381x over previous
#include <cuda_runtime.h>
#include <cuda_bf16.h>
#include <cstdint>

#define NUM_USERS 20000
#define EMBED_DIM 64
#define KSEL 6          // K+1 = 6 candidates, drop the max, keep 5
#define KNB  5
#define THREADS 256
#define BATCH 4096
#define ROW4 (NUM_USERS / 4)        // 5000 float4 per row
#define UNROLL 5
#define SUPER (THREADS * UNROLL)    // 1280 float4 per superblock
#define NSUPER 4                    // 4*1280 = 5120 >= 5000
#define T_FILT 0.998f               // static filter: E[survivors] ~ 40 of 20000
#define CAP 512                     // survivor buffer capacity (2 per thread)

static __device__ __forceinline__ unsigned long long umax64(unsigned long long a,
                                                            unsigned long long b) {
    return a > b ? a : b;
}

static __device__ __forceinline__ unsigned long long pack_key(float f, unsigned idx) {
    return ((unsigned long long)__float_as_uint(f) << 32) | (unsigned)(~idx);
}

// Branchless sorted insert (fallback path only). Static indices -> registers.
static __device__ __forceinline__ void insert6(unsigned long long (&top)[KSEL],
                                               unsigned long long key) {
#pragma unroll
    for (int i = 0; i < KSEL; i++) {
        unsigned long long hi = (top[i] > key) ? top[i] : key;
        unsigned long long lo = (top[i] > key) ? key : top[i];
        top[i] = hi;
        key = lo;
    }
}

// Block-wide u64 max reduce; result valid in winners_slot for all threads
// after the trailing __syncthreads().
static __device__ __forceinline__ unsigned long long
block_max64(unsigned long long cand, unsigned long long* warp_max,
            unsigned long long* winner_slot, int tid) {
    unsigned long long m = cand;
#pragma unroll
    for (int off = 16; off > 0; off >>= 1)
        m = umax64(m, __shfl_xor_sync(0xffffffffu, m, off));
    if ((tid & 31) == 0) warp_max[tid >> 5] = m;
    __syncthreads();
    if (tid < 32) {
        unsigned long long mm = (tid < (THREADS / 32)) ? warp_max[tid] : 0ULL;
#pragma unroll
        for (int off = 4; off > 0; off >>= 1)
            mm = umax64(mm, __shfl_xor_sync(0xffffffffu, mm, off));
        if (tid == 0) *winner_slot = mm;
    }
    __syncthreads();
    return *winner_slot;
}

__global__ void __launch_bounds__(THREADS, 4)
topk_blend_kernel(const int* __restrict__ user_idx,
                  const float* __restrict__ emb,
                  const float* __restrict__ cooc,
                  float* __restrict__ out)
{
    const int b   = blockIdx.x;
    const int tid = threadIdx.x;
    const int u   = user_idx[b];

    const float4* row4 = reinterpret_cast<const float4*>(cooc + (size_t)u * NUM_USERS);

    __shared__ int                cnt;
    __shared__ unsigned long long buf[CAP];
    __shared__ unsigned long long warp_max[THREADS / 32];
    __shared__ unsigned long long winners[KSEL];

    if (tid == 0) cnt = 0;
    __syncthreads();

    // ---- pass 1: static-threshold filter (hot loop: loads + max tree only) ----
#pragma unroll
    for (int s = 0; s < NSUPER; s++) {
        const int i0 = s * SUPER + tid;

        float4 v[UNROLL];
        if (s < NSUPER - 1) {
            // provably in-bounds: max ii = 2*1280 + 255 + 4*256 = 3839 < 5000
#pragma unroll
            for (int j = 0; j < UNROLL; j++)
                v[j] = row4[i0 + j * THREADS];
        } else {
#pragma unroll
            for (int j = 0; j < UNROLL; j++) {
                int ii = i0 + j * THREADS;
                bool ok = (ii < ROW4);
                v[j] = row4[ok ? ii : 0];
                if (!ok) { v[j].x = v[j].y = v[j].z = v[j].w = -1.0f; }
            }
        }

        float m = -1.0f;
#pragma unroll
        for (int j = 0; j < UNROLL; j++)
            m = fmaxf(m, fmaxf(fmaxf(v[j].x, v[j].y), fmaxf(v[j].z, v[j].w)));

        if (m > T_FILT) {
            // rare: push survivors into smem buffer
#pragma unroll
            for (int j = 0; j < UNROLL; j++) {
                const unsigned base = (unsigned)((i0 + j * THREADS) * 4);
#pragma unroll
                for (int c = 0; c < 4; c++) {
                    float f = (c == 0) ? v[j].x : (c == 1) ? v[j].y
                             : (c == 2) ? v[j].z : v[j].w;
                    if (f > T_FILT) {
                        int pos = atomicAdd(&cnt, 1);
                        if (pos < CAP) buf[pos] = pack_key(f, base + c);
                    }
                }
            }
        }
    }
    __syncthreads();
    const int n = cnt;   // block-uniform

    if (n >= KSEL && n <= CAP) {
        // ---- fast selection: 6-round max-reduce with removal over survivors ----
        unsigned long long k0 = (tid < n)           ? buf[tid]           : 0ULL;
        unsigned long long k1 = (tid + THREADS < n) ? buf[tid + THREADS] : 0ULL;
#pragma unroll
        for (int r = 0; r < KSEL; r++) {
            unsigned long long w =
                block_max64(umax64(k0, k1), warp_max, &winners[r], tid);
            if (k0 == w)      k0 = 0ULL;   // keys unique (idx embedded)
            else if (k1 == w) k1 = 0ULL;
        }
    } else {
        // ---- fallback (astronomically rare, but exact): full top-6 scan ----
        unsigned long long top[KSEL];
#pragma unroll
        for (int i = 0; i < KSEL; i++) top[i] = 0ULL;
        float thresh = 0.0f;

#pragma unroll
        for (int s = 0; s < NSUPER; s++) {
            const int i0 = s * SUPER + tid;
            float4 v[UNROLL];
#pragma unroll
            for (int j = 0; j < UNROLL; j++) {
                int ii = i0 + j * THREADS;
                bool ok = (ii < ROW4);
                v[j] = row4[ok ? ii : 0];
                if (!ok) { v[j].x = v[j].y = v[j].z = v[j].w = -1.0f; }
            }
            float m = -1.0f;
#pragma unroll
            for (int j = 0; j < UNROLL; j++)
                m = fmaxf(m, fmaxf(fmaxf(v[j].x, v[j].y), fmaxf(v[j].z, v[j].w)));
            if (m > thresh) {
#pragma unroll
                for (int j = 0; j < UNROLL; j++) {
                    const unsigned base = (unsigned)((i0 + j * THREADS) * 4);
#pragma unroll
                    for (int c = 0; c < 4; c++) {
                        float f = (c == 0) ? v[j].x : (c == 1) ? v[j].y
                                 : (c == 2) ? v[j].z : v[j].w;
                        if (f > thresh) insert6(top, pack_key(f, base + c));
                    }
                }
                thresh = __uint_as_float((unsigned)(top[KSEL - 1] >> 32));
            }
        }

        int ptr = 0;
#pragma unroll
        for (int r = 0; r < KSEL; r++) {
            unsigned long long cand;
            switch (ptr) {
                case 0: cand = top[0]; break;
                case 1: cand = top[1]; break;
                case 2: cand = top[2]; break;
                case 3: cand = top[3]; break;
                case 4: cand = top[4]; break;
                case 5: cand = top[5]; break;
                default: cand = 0ULL; break;
            }
            unsigned long long w = block_max64(cand, warp_max, &winners[r], tid);
            if (ptr < KSEL && cand == w) ptr++;
        }
    }

    // ---- epilogue: softmax over winners[1..5], blend embeddings ----
    if (tid < EMBED_DIM) {
        float smax = __uint_as_float((unsigned)(winners[1] >> 32));
        float sum = 0.0f;
        float acc = 0.0f;
#pragma unroll
        for (int j = 0; j < KNB; j++) {
            unsigned long long k = winners[j + 1];
            float    s    = __uint_as_float((unsigned)(k >> 32));
            unsigned sidx = ~(unsigned)(k & 0xffffffffULL);
            float    e    = __expf(s - smax);
            sum += e;
            acc  = fmaf(e, emb[(size_t)sidx * EMBED_DIM + tid], acc);
        }
        float blended = acc / sum;
        out[(size_t)b * EMBED_DIM + tid] =
            fmaf(0.7f, emb[(size_t)u * EMBED_DIM + tid], 0.3f * blended);
    }
}

extern "C" void kernel_launch(void* const* d_in, const int* in_sizes, int n_in,
                              void* d_out, int out_size)
{
    const int*   user_idx = (const int*)d_in[0];
    const float* emb      = (const float*)d_in[1];
    const float* cooc     = (const float*)d_in[2];
    float*       out      = (float*)d_out;

    topk_blend_kernel<<<BATCH, THREADS>>>(user_idx, emb, cooc, out);
}

// round 10
// speedup vs baseline: 6.5420x; 1.6935x over previous
#include <cuda_runtime.h>
#include <cuda_bf16.h>
#include <cstdint>

#define NUM_USERS 20000
#define EMBED_DIM 64
#define KSEL 6          // K+1 = 6 candidates, drop the max, keep 5
#define KNB  5
#define THREADS 256
#define BATCH 4096
#define ROW4 (NUM_USERS / 4)        // 5000 float4 per row
#define STAGE_F4 1280               // float4 per pipeline stage (20 KB)
#define NSTAGE 4                    // 3*1280 + 1160 = 5000
#define LAST_F4 (ROW4 - 3 * STAGE_F4)   // 1160
#define T_FILT 0.998f               // static filter: E[survivors] ~ 40 of 20000
#define CAP 512

static __device__ __forceinline__ unsigned long long umax64(unsigned long long a,
                                                            unsigned long long b) {
    return a > b ? a : b;
}

static __device__ __forceinline__ unsigned long long pack_key(float f, unsigned idx) {
    return ((unsigned long long)__float_as_uint(f) << 32) | (unsigned)(~idx);
}

static __device__ __forceinline__ uint32_t smem_u32(const void* p) {
    uint32_t a;
    asm("{ .reg .u64 t; cvta.to.shared.u64 t, %1; cvt.u32.u64 %0, t; }"
        : "=r"(a) : "l"(p));
    return a;
}

static __device__ __forceinline__ void mbar_init(uint32_t mbar, uint32_t cnt) {
    asm volatile("mbarrier.init.shared.b64 [%0], %1;" :: "r"(mbar), "r"(cnt) : "memory");
}

static __device__ __forceinline__ void mbar_expect_tx(uint32_t mbar, uint32_t bytes) {
    asm volatile("mbarrier.arrive.expect_tx.shared.b64 _, [%0], %1;"
                 :: "r"(mbar), "r"(bytes) : "memory");
}

static __device__ __forceinline__ void bulk_g2s(uint32_t dst, const void* src,
                                                uint32_t bytes, uint32_t mbar) {
    asm volatile(
        "cp.async.bulk.shared::cta.global.mbarrier::complete_tx::bytes "
        "[%0], [%1], %2, [%3];"
        :: "r"(dst), "l"(src), "r"(bytes), "r"(mbar) : "memory");
}

static __device__ __forceinline__ void mbar_wait(uint32_t mbar, uint32_t parity) {
    uint32_t done;
    asm volatile(
        "{\n\t.reg .pred p;\n\t"
        "mbarrier.try_wait.parity.acquire.cta.shared::cta.b64 p, [%1], %2;\n\t"
        "selp.b32 %0, 1, 0, p;\n\t}"
        : "=r"(done) : "r"(mbar), "r"(parity) : "memory");
    if (!done) {
        asm volatile(
            "{\n\t.reg .pred P1;\n\t"
            "WL_%=:\n\t"
            "mbarrier.try_wait.parity.acquire.cta.shared::cta.b64 P1, [%0], %1, 0x989680;\n\t"
            "@P1 bra.uni WD_%=;\n\t"
            "bra.uni WL_%=;\n\t"
            "WD_%=:\n\t}"
            :: "r"(mbar), "r"(parity) : "memory");
    }
}

// Branchless sorted insert (fallback only). Static indices -> registers.
static __device__ __forceinline__ void insert6(unsigned long long (&top)[KSEL],
                                               unsigned long long key) {
#pragma unroll
    for (int i = 0; i < KSEL; i++) {
        unsigned long long hi = (top[i] > key) ? top[i] : key;
        unsigned long long lo = (top[i] > key) ? key : top[i];
        top[i] = hi;
        key = lo;
    }
}

static __device__ __forceinline__ unsigned long long
block_max64(unsigned long long cand, unsigned long long* warp_max,
            unsigned long long* winner_slot, int tid) {
    unsigned long long m = cand;
#pragma unroll
    for (int off = 16; off > 0; off >>= 1)
        m = umax64(m, __shfl_xor_sync(0xffffffffu, m, off));
    if ((tid & 31) == 0) warp_max[tid >> 5] = m;
    __syncthreads();
    if (tid < 32) {
        unsigned long long mm = (tid < (THREADS / 32)) ? warp_max[tid] : 0ULL;
#pragma unroll
        for (int off = 4; off > 0; off >>= 1)
            mm = umax64(mm, __shfl_xor_sync(0xffffffffu, mm, off));
        if (tid == 0) *winner_slot = mm;
    }
    __syncthreads();
    return *winner_slot;
}

__global__ void __launch_bounds__(THREADS, 4)
topk_blend_kernel(const int* __restrict__ user_idx,
                  const float* __restrict__ emb,
                  const float* __restrict__ cooc,
                  float* __restrict__ out)
{
    __shared__ __align__(128) float4 sbuf[2][STAGE_F4];      // 40 KB double buffer
    __shared__ __align__(8) unsigned long long mbar[2];
    __shared__ unsigned long long buf[CAP];
    __shared__ unsigned long long warp_max[THREADS / 32];
    __shared__ unsigned long long winners[KSEL];
    __shared__ int cnt;

    const int b   = blockIdx.x;
    const int tid = threadIdx.x;
    const int u   = user_idx[b];

    const float4* row4 = reinterpret_cast<const float4*>(cooc + (size_t)u * NUM_USERS);

    const uint32_t mb0 = smem_u32(&mbar[0]);
    const uint32_t mb1 = smem_u32(&mbar[1]);
    const uint32_t sb0 = smem_u32(&sbuf[0][0]);
    const uint32_t sb1 = smem_u32(&sbuf[1][0]);

    if (tid == 0) {
        cnt = 0;
        mbar_init(mb0, 1);
        mbar_init(mb1, 1);
    }
    __syncthreads();

    if (tid == 0) {
        mbar_expect_tx(mb0, STAGE_F4 * 16);
        bulk_g2s(sb0, row4, STAGE_F4 * 16, mb0);
        mbar_expect_tx(mb1, STAGE_F4 * 16);
        bulk_g2s(sb1, row4 + STAGE_F4, STAGE_F4 * 16, mb1);
    }

    // ---- pass 1: pipelined filter out of smem ----
#pragma unroll
    for (int s = 0; s < NSTAGE; s++) {
        const uint32_t mb = (s & 1) ? mb1 : mb0;
        mbar_wait(mb, (s >> 1) & 1);

        const float4* stage = sbuf[s & 1];
        float4 v[5];
        if (s < NSTAGE - 1) {
#pragma unroll
            for (int j = 0; j < 5; j++)
                v[j] = stage[tid + j * THREADS];
        } else {
#pragma unroll
            for (int j = 0; j < 5; j++) {
                int ii = tid + j * THREADS;
                bool ok = (ii < LAST_F4);
                v[j] = stage[ok ? ii : 0];
                if (!ok) { v[j].x = v[j].y = v[j].z = v[j].w = -1.0f; }
            }
        }

        float m = -1.0f;
#pragma unroll
        for (int j = 0; j < 5; j++)
            m = fmaxf(m, fmaxf(fmaxf(v[j].x, v[j].y), fmaxf(v[j].z, v[j].w)));

        if (m > T_FILT) {
#pragma unroll
            for (int j = 0; j < 5; j++) {
                const unsigned base = (unsigned)((s * STAGE_F4 + tid + j * THREADS) * 4);
#pragma unroll
                for (int c = 0; c < 4; c++) {
                    float f = (c == 0) ? v[j].x : (c == 1) ? v[j].y
                             : (c == 2) ? v[j].z : v[j].w;
                    if (f > T_FILT) {
                        int pos = atomicAdd(&cnt, 1);
                        if (pos < CAP) buf[pos] = pack_key(f, base + c);
                    }
                }
            }
        }

        __syncthreads();   // everyone done reading sbuf[s&1] (and stage-s pushes visible)

        if (s + 2 < NSTAGE && tid == 0) {
            const int ns = s + 2;
            const uint32_t bytes = (ns == NSTAGE - 1) ? (LAST_F4 * 16) : (STAGE_F4 * 16);
            const uint32_t dst = (s & 1) ? sb1 : sb0;
            mbar_expect_tx(mb, bytes);
            bulk_g2s(dst, row4 + ns * STAGE_F4, bytes, mb);
        }
    }

    const int n = cnt;   // block-uniform after the last __syncthreads()

    if (n >= KSEL && n <= CAP) {
        // ---- fast selection: 6-round max-reduce with removal ----
        unsigned long long k0 = (tid < n)           ? buf[tid]           : 0ULL;
        unsigned long long k1 = (tid + THREADS < n) ? buf[tid + THREADS] : 0ULL;
#pragma unroll
        for (int r = 0; r < KSEL; r++) {
            unsigned long long w =
                block_max64(umax64(k0, k1), warp_max, &winners[r], tid);
            if (k0 == w)      k0 = 0ULL;   // keys unique (idx embedded)
            else if (k1 == w) k1 = 0ULL;
        }
    } else {
        // ---- exact fallback: full global rescan (cold path) ----
        unsigned long long top[KSEL];
#pragma unroll
        for (int i = 0; i < KSEL; i++) top[i] = 0ULL;
        float thresh = -1.0f;

        for (int i = tid; i < ROW4; i += THREADS) {
            float4 v = row4[i];
            const unsigned base = (unsigned)(i * 4);
            float m = fmaxf(fmaxf(v.x, v.y), fmaxf(v.z, v.w));
            if (m > thresh) {
#pragma unroll
                for (int c = 0; c < 4; c++) {
                    float f = (c == 0) ? v.x : (c == 1) ? v.y : (c == 2) ? v.z : v.w;
                    if (f > thresh) insert6(top, pack_key(f, base + c));
                }
                thresh = __uint_as_float((unsigned)(top[KSEL - 1] >> 32));
            }
        }

        int ptr = 0;
#pragma unroll
        for (int r = 0; r < KSEL; r++) {
            unsigned long long cand;
            switch (ptr) {
                case 0: cand = top[0]; break;
                case 1: cand = top[1]; break;
                case 2: cand = top[2]; break;
                case 3: cand = top[3]; break;
                case 4: cand = top[4]; break;
                case 5: cand = top[5]; break;
                default: cand = 0ULL; break;
            }
            unsigned long long w = block_max64(cand, warp_max, &winners[r], tid);
            if (ptr < KSEL && cand == w) ptr++;
        }
    }

    // ---- epilogue: softmax over winners[1..5], blend embeddings ----
    if (tid < EMBED_DIM) {
        float smax = __uint_as_float((unsigned)(winners[1] >> 32));
        float sum = 0.0f;
        float acc = 0.0f;
#pragma unroll
        for (int j = 0; j < KNB; j++) {
            unsigned long long k = winners[j + 1];
            float    s    = __uint_as_float((unsigned)(k >> 32));
            unsigned sidx = ~(unsigned)(k & 0xffffffffULL);
            float    e    = __expf(s - smax);
            sum += e;
            acc  = fmaf(e, emb[(size_t)sidx * EMBED_DIM + tid], acc);
        }
        float blended = acc / sum;
        out[(size_t)b * EMBED_DIM + tid] =
            fmaf(0.7f, emb[(size_t)u * EMBED_DIM + tid], 0.3f * blended);
    }
}

extern "C" void kernel_launch(void* const* d_in, const int* in_sizes, int n_in,
                              void* d_out, int out_size)
{
    const int*   user_idx = (const int*)d_in[0];
    const float* emb      = (const float*)d_in[1];
    const float* cooc     = (const float*)d_in[2];
    float*       out      = (float*)d_out;

    topk_blend_kernel<<<BATCH, THREADS>>>(user_idx, emb, cooc, out);
}